// round 9
// baseline (speedup 1.0000x reference)
#include <cuda_runtime.h>
#include <math.h>
#include <stdint.h>

#define B 64
#define H 128
#define E 128
#define NL 4
#define S 8192
#define V 50257
#define FOURH 512
#define CHUNKS 128   // S / ROWS
#define ROWS 64
#define NCPY 4       // parallel CE memcpy chunks

#define SZ_LOGITS (B*V)
#define OFF_C  (SZ_LOGITS)
#define OFF_H  (OFF_C + NL*B*H)
#define OFF_ATTN (OFF_H + NL*B*H)

typedef unsigned long long ull;

// ---------------- device scratch (no allocations allowed) ----------------
__device__ __align__(16) float g_x[B*H];
__device__ __align__(16) float g_r[B*H];
__device__ float g_cK[B];
__device__ float g_pm[B*CHUNKS];
__device__ float g_pl[B*CHUNKS];
__device__ __align__(16) float g_pacc[B*CHUNKS*H];
__device__ __align__(16) float g_hln[B*H];
__device__ int g_done = 0;   // LSTM blocks finished (target 32)

__device__ __forceinline__ float warp_sum(float v) {
#pragma unroll
    for (int o = 16; o > 0; o >>= 1) v += __shfl_xor_sync(0xffffffffu, v, o);
    return v;
}
__device__ __forceinline__ float sigf(float x) { return 1.f / (1.f + __expf(-x)); }

__device__ __forceinline__ ull fma2(ull a, ull b, ull c) {
    ull d;
    asm("fma.rn.f32x2 %0, %1, %2, %3;" : "=l"(d) : "l"(a), "l"(b), "l"(c));
    return d;
}
__device__ __forceinline__ ull bcast2(float f) {
    ull d;
    asm("mov.b64 %0, {%1, %1};" : "=l"(d) : "f"(f));
    return d;
}
__device__ __forceinline__ void spin_gate(int* flag, int target, int tid) {
    if (tid == 0) {
        int fv;
        do {
            asm volatile("ld.global.cg.b32 %0, [%1];" : "=r"(fv) : "l"(flag));
            if (fv < target) __nanosleep(64);
        } while (fv < target);
    }
    __syncthreads();
    __threadfence();   // acquire
}

// ---------------- shared-memory role layouts -------------------------------
struct LstmSmem {
    ull xs2[2][H];
    ull hs2[2][H];
    float gp[2][2][FOURH];
    float qs[2][H];
};
struct FlashSmem {
    float acc[8][H];
    float m[8];
    float l[8];
};
union PreSmem { LstmSmem lstm; FlashSmem fl; };

// ============ LSTM role ====================================================
__device__ void lstm_role(
    LstmSmem& sm, int b0,
    const int* __restrict__ token_id, const float* __restrict__ c0,
    const float* __restrict__ h0, const float* __restrict__ emb,
    const float* __restrict__ Wi, const float* __restrict__ Uh,
    const float* __restrict__ bL, const float* __restrict__ Wq,
    const float* __restrict__ bq, const float* __restrict__ Wk,
    const float* __restrict__ bk, float* __restrict__ out)
{
    int tid = threadIdx.x;

    for (int idx = tid; idx < 2*H; idx += 256) {
        int bb = idx >> 7, i = idx & 127;
        float v = emb[(size_t)token_id[b0+bb]*E + i];
        sm.xs2[bb][i] = bcast2(v);
    }

    int khalf = tid >> 7;
    int tc = tid & 127;
    int cbase = tc * 4;

    for (int l = 0; l < NL; l++) {
        for (int idx = tid; idx < 2*H; idx += 256) {
            int bb = idx >> 7, i = idx & 127;
            float v = h0[((size_t)l*B + b0 + bb)*H + i];
            sm.hs2[bb][i] = bcast2(v);
        }
        __syncthreads();

        ull a00 = 0, a01 = 0, a10 = 0, a11 = 0;
        const ulonglong2* Wi2 = (const ulonglong2*)(Wi + (size_t)l*E*FOURH);
        const ulonglong2* Uh2 = (const ulonglong2*)(Uh + (size_t)l*H*FOURH);
        int k0 = khalf * 64;
#pragma unroll 4
        for (int k = k0; k < k0 + 64; k++) {
            ulonglong2 w = Wi2[k*(FOURH/4) + tc];
            ulonglong2 u = Uh2[k*(FOURH/4) + tc];
            ull x0 = sm.xs2[0][k], x1 = sm.xs2[1][k];
            ull hh0 = sm.hs2[0][k], hh1 = sm.hs2[1][k];
            a00 = fma2(w.x, x0, a00);  a01 = fma2(w.y, x0, a01);
            a00 = fma2(u.x, hh0, a00); a01 = fma2(u.y, hh0, a01);
            a10 = fma2(w.x, x1, a10);  a11 = fma2(w.y, x1, a11);
            a10 = fma2(u.x, hh1, a10); a11 = fma2(u.y, hh1, a11);
        }
        *(ull*)&sm.gp[khalf][0][cbase]   = a00;
        *(ull*)&sm.gp[khalf][0][cbase+2] = a01;
        *(ull*)&sm.gp[khalf][1][cbase]   = a10;
        *(ull*)&sm.gp[khalf][1][cbase+2] = a11;
        __syncthreads();

        {
            int bb = tid >> 7, i = tid & 127;
            const float* bb_l = bL + l*FOURH;
            float ig = sm.gp[0][bb][i]       + sm.gp[1][bb][i]       + bb_l[i];
            float fg = sm.gp[0][bb][128 + i] + sm.gp[1][bb][128 + i] + bb_l[128 + i];
            float gg = sm.gp[0][bb][256 + i] + sm.gp[1][bb][256 + i] + bb_l[256 + i];
            float og = sm.gp[0][bb][384 + i] + sm.gp[1][bb][384 + i] + bb_l[384 + i];
            size_t ofs = ((size_t)l*B + b0 + bb)*H + i;
            float cprev = c0[ofs];
            float cn = sigf(fg)*cprev + sigf(ig)*tanhf(gg);
            float hn = sigf(og)*tanhf(cn);
            out[OFF_C + ofs] = cn;
            out[OFF_H + ofs] = hn;
            sm.xs2[bb][i] = bcast2(hn);
        }
    }
    __syncthreads();

    for (int idx = tid; idx < 2*H; idx += 256) {
        int bb = idx >> 7, i = idx & 127;
        g_x[(b0+bb)*H + i] = ((const float2*)&sm.xs2[bb][i])->x;
    }

    {
        int bb = tid >> 7, j = tid & 127;
        float acc = bq[j];
#pragma unroll 8
        for (int i = 0; i < H; i++)
            acc += ((const float2*)&sm.xs2[bb][i])->x * Wq[i*H + j];
        sm.qs[bb][j] = acc;
    }
    __syncthreads();

    int wid = tid >> 5, lane = tid & 31;
    for (int row = wid; row < 2*H; row += 8) {
        int bb = row >> 7, i = row & 127;
        float4 wv = ((const float4*)(Wk + (size_t)i*H))[lane];
        float4 qv = ((const float4*)sm.qs[bb])[lane];
        float d = wv.x*qv.x + wv.y*qv.y + wv.z*qv.z + wv.w*qv.w;
        d = warp_sum(d);
        if (lane == 0) g_r[(b0+bb)*H + i] = d;
    }
    if (wid < 2) {
        int bb = wid;
        float p = 0.f;
        for (int j = lane; j < H; j += 32) p += bk[j] * sm.qs[bb][j];
        p = warp_sum(p);
        if (lane == 0) g_cK[b0+bb] = p;
    }
    __syncthreads();
    __threadfence();                    // release
    if (tid == 0) atomicAdd(&g_done, 1);
}

// ==== K_PRE: 32 LSTM blocks + READ-ONLY flash pass over active region =====
// The attn_mem copy is done concurrently by CE memcpys — flash only reads.
__global__ __launch_bounds__(256) void k_pre(
    const float* __restrict__ attn_mem, const int* __restrict__ step_p,
    const int* __restrict__ token_id, const float* __restrict__ c0,
    const float* __restrict__ h0, const float* __restrict__ emb,
    const float* __restrict__ Wi, const float* __restrict__ Uh,
    const float* __restrict__ bL, const float* __restrict__ Wq,
    const float* __restrict__ bq, const float* __restrict__ Wk,
    const float* __restrict__ bk, float* __restrict__ out)
{
    __shared__ PreSmem sm;

    int id = blockIdx.x;
    int tid = threadIdx.x, wid = tid >> 5, lane = tid & 31;

    if (id < 32) {
        lstm_role(sm.lstm, id*2, token_id, c0, h0, emb, Wi, Uh, bL,
                  Wq, bq, Wk, bk, out);
        return;
    }

    int w = id - 32;
    int b = w & 63;
    int chunk = w >> 6;
    int step = *step_p;
    if (chunk*ROWS > step) return;      // inactive: nothing to do (CE copies)

    spin_gate(&g_done, 32, tid);        // LSTM results ready

    int base = chunk*ROWS + wid*8;
    const float4* src = (const float4*)(attn_mem + (size_t)b*S*H);
    const float scl = 0.08838834764831843f;   // 1/sqrt(128)

    float4 rf;
    {
        const float* rp = g_r + b*H + lane*4;
        rf.x = __ldcg(rp); rf.y = __ldcg(rp+1); rf.z = __ldcg(rp+2); rf.w = __ldcg(rp+3);
    }
    float cK = __ldcg(&g_cK[b]);

    float4 v[8];
#pragma unroll
    for (int t = 0; t < 8; t++) {
        int s = base + t;
        if (s == step) {
            const float* xp = g_x + b*H + lane*4;
            v[t].x = __ldcg(xp); v[t].y = __ldcg(xp+1);
            v[t].z = __ldcg(xp+2); v[t].w = __ldcg(xp+3);
        } else {
            v[t] = __ldcs(&src[(size_t)s*32 + lane]);
        }
    }

    float d[8];
#pragma unroll
    for (int t = 0; t < 8; t++)
        d[t] = v[t].x*rf.x + v[t].y*rf.y + v[t].z*rf.z + v[t].w*rf.w;
#pragma unroll
    for (int o = 16; o > 0; o >>= 1) {
#pragma unroll
        for (int t = 0; t < 8; t++)
            d[t] += __shfl_xor_sync(0xffffffffu, d[t], o);
    }

    float m = -INFINITY;
#pragma unroll
    for (int t = 0; t < 8; t++) {
        d[t] = (base + t <= step) ? (d[t] + cK) * scl : -INFINITY;
        m = fmaxf(m, d[t]);
    }
    float l = 0.f;
    float4 acc = {0.f, 0.f, 0.f, 0.f};
#pragma unroll
    for (int t = 0; t < 8; t++) {
        float ww = (base + t <= step) ? __expf(d[t] - m) : 0.f;
        l += ww;
        acc.x += ww*v[t].x; acc.y += ww*v[t].y;
        acc.z += ww*v[t].z; acc.w += ww*v[t].w;
    }
    ((float4*)sm.fl.acc[wid])[lane] = acc;
    if (lane == 0) { sm.fl.m[wid] = m; sm.fl.l[wid] = l; }
    __syncthreads();

    if (tid < H) {
        float M = sm.fl.m[0];
#pragma unroll
        for (int ww = 1; ww < 8; ww++) M = fmaxf(M, sm.fl.m[ww]);
        float a = 0.f, L = 0.f;
#pragma unroll
        for (int ww = 0; ww < 8; ww++) {
            float e = __expf(sm.fl.m[ww] - M);   // exp(-inf) = 0
            a += sm.fl.acc[ww][tid] * e;
            L += sm.fl.l[ww] * e;
        }
        g_pacc[((size_t)b*CHUNKS + chunk)*H + tid] = a;
        if (tid == 0) { g_pm[b*CHUNKS + chunk] = M; g_pl[b*CHUNKS + chunk] = L; }
    }
}

// ==== K3: combine partials -> ctx -> mix -> tanh -> LayerNorm ============
__global__ __launch_bounds__(256) void k_reduce(
    const int* __restrict__ step_p,
    const float* __restrict__ Wv, const float* __restrict__ bv,
    const float* __restrict__ Wmix, const float* __restrict__ bmix,
    const float* __restrict__ lns, const float* __restrict__ lnb)
{
    __shared__ float es[CHUNKS];
    __shared__ float red[128];
    __shared__ float part[256];
    __shared__ float cp[H], xsm[H], ctxs[H];

    int b = blockIdx.x;
    int tid = threadIdx.x;
    int t = tid & 127, half = tid >> 7;
    int nact = (*step_p >> 6) + 1;

    if (b == 0 && tid == 0) g_done = 0;   // reset for next replay (k_pre done)

    if (tid < 128) {
        float pm = (tid < nact) ? g_pm[b*CHUNKS + tid] : -INFINITY;
        red[tid] = pm;
    }
    __syncthreads();
    for (int o = 64; o > 0; o >>= 1) {
        if (tid < o) red[tid] = fmaxf(red[tid], red[tid+o]);
        __syncthreads();
    }
    float M = red[0];
    __syncthreads();

    if (tid < 128) {
        float pm = (tid < nact) ? g_pm[b*CHUNKS + tid] : -INFINITY;
        float pl = (tid < nact) ? g_pl[b*CHUNKS + tid] : 0.f;
        float e = __expf(pm - M);
        es[tid] = e;
        red[tid] = pl * e;
    }
    __syncthreads();
    for (int o = 64; o > 0; o >>= 1) {
        if (tid < o) red[tid] += red[tid+o];
        __syncthreads();
    }
    float L = red[0];
    __syncthreads();

    {
        float a = 0.f;
#pragma unroll 4
        for (int c = half; c < nact; c += 2)
            a += g_pacc[((size_t)b*CHUNKS + c)*H + t] * es[c];
        part[tid] = a;
    }
    __syncthreads();
    if (tid < 128) {
        cp[t] = (part[t] + part[t+128]) / L;
        xsm[t] = g_x[b*H + t];
    }
    __syncthreads();

    {
        float cv = 0.f;
        int i0 = half*64;
#pragma unroll 8
        for (int i = i0; i < i0 + 64; i++) cv += cp[i] * Wv[i*H + t];
        part[tid] = cv;
    }
    __syncthreads();
    if (tid < 128) ctxs[t] = part[t] + part[t+128] + bv[t];
    __syncthreads();

    {
        float hm = 0.f;
        if (half == 0) {
#pragma unroll 8
            for (int i = 0; i < 128; i++) hm += xsm[i] * Wmix[i*H + t];
        } else {
#pragma unroll 8
            for (int i = 0; i < 128; i++) hm += ctxs[i] * Wmix[(H+i)*H + t];
        }
        part[tid] = hm;
    }
    __syncthreads();

    float hv = 0.f;
    if (tid < 128) {
        hv = tanhf(part[t] + part[t+128] + bmix[t]);
        red[t] = hv;
    }
    __syncthreads();
    for (int o = 64; o > 0; o >>= 1) {
        if (tid < o) red[tid] += red[tid+o];
        __syncthreads();
    }
    float mu = red[0] * (1.f/128.f);
    __syncthreads();
    float dv = hv - mu;
    if (tid < 128) red[t] = dv*dv;
    __syncthreads();
    for (int o = 64; o > 0; o >>= 1) {
        if (tid < o) red[tid] += red[tid+o];
        __syncthreads();
    }
    float var = red[0] * (1.f/128.f);

    if (tid < 128)
        g_hln[b*H + t] = dv * rsqrtf(var + 1e-6f) * lns[t] + lnb[t];
}

// ==== K4: logits (+ step-row splice by blockIdx.x==0 blocks) ==============
// Runs AFTER the CE memcpys join, so the splice lands on copied data.
__global__ __launch_bounds__(256, 4) void k_logits(
    const int* __restrict__ step_p,
    const float* __restrict__ Wout, const float* __restrict__ bout,
    float* __restrict__ out)
{
    __shared__ ull hsu[H*8];
    int tid = threadIdx.x;
    int bq = blockIdx.y;

    // splice x into the step row of the CE-copied attn_mem (16 batches/block)
    if (blockIdx.x == 0) {
        int step = *step_p;
        for (int idx = tid; idx < 16*H; idx += 256) {
            int bb = bq*16 + (idx >> 7);
            int i = idx & 127;
            out[OFF_ATTN + (size_t)bb*S*H + (size_t)step*H + i] = g_x[bb*H + i];
        }
    }

    float* hsf = (float*)hsu;
    for (int idx = tid; idx < 16*H; idx += 256) {
        int k = idx >> 4, bb = idx & 15;
        hsf[k*16 + bb] = g_hln[(bq*16 + bb)*H + k];
    }
    __syncthreads();

    int base = blockIdx.x * 512;
    int ca = base + tid;
    int cb = ca + 256;
    int ca_ok = (ca < V), cb_ok = (cb < V);
    int ca_c = ca_ok ? ca : (V-1);
    int cb_c = cb_ok ? cb : (V-1);

    ull acc0[8], acc1[8];
#pragma unroll
    for (int i = 0; i < 8; i++) { acc0[i] = 0ULL; acc1[i] = 0ULL; }

#pragma unroll 4
    for (int k = 0; k < H; k++) {
        float wa = Wout[(size_t)k*V + ca_c];
        float wb = Wout[(size_t)k*V + cb_c];
        ull w2a = bcast2(wa);
        ull w2b = bcast2(wb);
        const ulonglong2* hp = (const ulonglong2*)(hsu + k*8);
#pragma unroll
        for (int p = 0; p < 4; p++) {
            ulonglong2 hv = hp[p];
            acc0[2*p]   = fma2(hv.x, w2a, acc0[2*p]);
            acc0[2*p+1] = fma2(hv.y, w2a, acc0[2*p+1]);
            acc1[2*p]   = fma2(hv.x, w2b, acc1[2*p]);
            acc1[2*p+1] = fma2(hv.y, w2b, acc1[2*p+1]);
        }
    }

    if (ca_ok) {
        float bo = bout[ca_c];
#pragma unroll
        for (int p = 0; p < 8; p++) {
            float f0, f1;
            asm("mov.b64 {%0, %1}, %2;" : "=f"(f0), "=f"(f1) : "l"(acc0[p]));
            int b0r = bq*16 + 2*p;
            out[(size_t)b0r*V + ca]     = f0 + bo;
            out[(size_t)(b0r+1)*V + ca] = f1 + bo;
        }
    }
    if (cb_ok) {
        float bo = bout[cb_c];
#pragma unroll
        for (int p = 0; p < 8; p++) {
            float f0, f1;
            asm("mov.b64 {%0, %1}, %2;" : "=f"(f0), "=f"(f1) : "l"(acc1[p]));
            int b0r = bq*16 + 2*p;
            out[(size_t)b0r*V + cb]     = f0 + bo;
            out[(size_t)(b0r+1)*V + cb] = f1 + bo;
        }
    }
}

// ---------------- streams/events created at static-init -------------------
static cudaStream_t g_cs[NCPY];
static cudaEvent_t  g_fork, g_join[NCPY];
static struct StreamInit {
    StreamInit() {
        for (int i = 0; i < NCPY; i++)
            cudaStreamCreateWithFlags(&g_cs[i], cudaStreamNonBlocking);
        cudaEventCreateWithFlags(&g_fork, cudaEventDisableTiming);
        for (int i = 0; i < NCPY; i++)
            cudaEventCreateWithFlags(&g_join[i], cudaEventDisableTiming);
    }
} g_stream_init;

// ==========================================================================
extern "C" void kernel_launch(void* const* d_in, const int* in_sizes, int n_in,
                              void* d_out, int out_size)
{
    const int*   token_id = (const int*)  d_in[0];
    const float* c0       = (const float*)d_in[1];
    const float* h0       = (const float*)d_in[2];
    const float* attn_mem = (const float*)d_in[3];
    const int*   step_p   = (const int*)  d_in[4];
    const float* emb      = (const float*)d_in[5];
    const float* Wi       = (const float*)d_in[6];
    const float* Uh       = (const float*)d_in[7];
    const float* bL       = (const float*)d_in[8];
    const float* Wq       = (const float*)d_in[9];
    const float* bq       = (const float*)d_in[10];
    const float* Wk       = (const float*)d_in[11];
    const float* bk       = (const float*)d_in[12];
    const float* Wv       = (const float*)d_in[13];
    const float* bv       = (const float*)d_in[14];
    const float* Wmix     = (const float*)d_in[15];
    const float* bmix     = (const float*)d_in[16];
    const float* lns      = (const float*)d_in[17];
    const float* lnb      = (const float*)d_in[18];
    const float* Wout     = (const float*)d_in[19];
    const float* bout     = (const float*)d_in[20];
    float* out = (float*)d_out;

    // fork: CE memcpys of the full attn_mem run concurrently with SM work
    cudaEventRecord(g_fork, 0);
    size_t qelem = (size_t)B*S*H / NCPY;        // floats per chunk
    for (int i = 0; i < NCPY; i++) {
        cudaStreamWaitEvent(g_cs[i], g_fork, 0);
        cudaMemcpyAsync(out + OFF_ATTN + i*qelem, attn_mem + i*qelem,
                        qelem*sizeof(float), cudaMemcpyDeviceToDevice, g_cs[i]);
        cudaEventRecord(g_join[i], g_cs[i]);
    }

    // main stream: LSTM + read-only flash, then reduce
    k_pre<<<32 + CHUNKS*B, 256>>>(attn_mem, step_p, token_id, c0, h0, emb,
                                  Wi, Uh, bL, Wq, bq, Wk, bk, out);
    k_reduce<<<B, 256>>>(step_p, Wv, bv, Wmix, bmix, lns, lnb);

    // join CE copies, then logits (+ step-row splice)
    for (int i = 0; i < NCPY; i++)
        cudaStreamWaitEvent(0, g_join[i], 0);
    dim3 g4((V + 511)/512, 4);
    k_logits<<<g4, 256>>>(step_p, Wout, bout, out);
}

// round 10
// speedup vs baseline: 1.1893x; 1.1893x over previous
#include <cuda_runtime.h>
#include <math.h>

#define B 64
#define H 128
#define E 128
#define NL 4
#define S 8192
#define V 50257
#define FOURH 512
#define CHUNKS 128   // S / ROWS
#define ROWS 64

#define SZ_LOGITS (B*V)
#define OFF_C  (SZ_LOGITS)
#define OFF_H  (OFF_C + NL*B*H)
#define OFF_ATTN (OFF_H + NL*B*H)

typedef unsigned long long ull;

// ---------------- device scratch (no allocations allowed) ----------------
__device__ __align__(16) float g_x[B*H];          // final hidden (x)
__device__ __align__(16) float g_r[B*H];          // Wk @ q  per batch
__device__ float g_cK[B];                          // bk . q
__device__ float g_pm[B*CHUNKS];
__device__ float g_pl[B*CHUNKS];
__device__ __align__(16) float g_pacc[B*CHUNKS*H]; // partial accumulators
__device__ __align__(16) float g_hln[B*H];

__device__ __forceinline__ float warp_sum(float v) {
#pragma unroll
    for (int o = 16; o > 0; o >>= 1) v += __shfl_xor_sync(0xffffffffu, v, o);
    return v;
}
__device__ __forceinline__ float sigf(float x) { return 1.f / (1.f + __expf(-x)); }

__device__ __forceinline__ ull fma2(ull a, ull b, ull c) {
    ull d;
    asm("fma.rn.f32x2 %0, %1, %2, %3;" : "=l"(d) : "l"(a), "l"(b), "l"(c));
    return d;
}
__device__ __forceinline__ ull bcast2(float f) {
    ull d;
    asm("mov.b64 %0, {%1, %1};" : "=l"(d) : "f"(f));
    return d;
}

// ============ K1: embed + 4-layer LSTM + q, r = Wk@q, cK = bk.q ============
// 32 blocks x 256 threads, 2 batches per block, f32x2 FMAs.
__global__ __launch_bounds__(256) void k_lstm(
    const int* __restrict__ token_id, const float* __restrict__ c0,
    const float* __restrict__ h0, const float* __restrict__ emb,
    const float* __restrict__ Wi, const float* __restrict__ Uh,
    const float* __restrict__ bL, const float* __restrict__ Wq,
    const float* __restrict__ bq, const float* __restrict__ Wk,
    const float* __restrict__ bk, float* __restrict__ out)
{
    __shared__ ull xs2[2][H];              // {x,x} broadcast pairs
    __shared__ ull hs2[2][H];              // {h,h} broadcast pairs
    __shared__ float gp[2][2][FOURH];      // [k-half][bb][col]
    __shared__ float qs[2][H];

    int tid = threadIdx.x;
    int b0 = blockIdx.x * 2;

    for (int idx = tid; idx < 2*H; idx += 256) {
        int bb = idx >> 7, i = idx & 127;
        float v = emb[(size_t)token_id[b0+bb]*E + i];
        xs2[bb][i] = bcast2(v);
    }

    int khalf = tid >> 7;        // 0 or 1: which half of k
    int tc = tid & 127;          // column group: cols [4tc, 4tc+4)
    int cbase = tc * 4;

    for (int l = 0; l < NL; l++) {
        for (int idx = tid; idx < 2*H; idx += 256) {
            int bb = idx >> 7, i = idx & 127;
            float v = h0[((size_t)l*B + b0 + bb)*H + i];
            hs2[bb][i] = bcast2(v);
        }
        __syncthreads();

        ull a00 = 0, a01 = 0, a10 = 0, a11 = 0;
        const ulonglong2* Wi2 = (const ulonglong2*)(Wi + (size_t)l*E*FOURH);
        const ulonglong2* Uh2 = (const ulonglong2*)(Uh + (size_t)l*H*FOURH);
        int k0 = khalf * 64;
#pragma unroll 4
        for (int k = k0; k < k0 + 64; k++) {
            ulonglong2 w = Wi2[k*(FOURH/4) + tc];
            ulonglong2 u = Uh2[k*(FOURH/4) + tc];
            ull x0 = xs2[0][k], x1 = xs2[1][k];
            ull hh0 = hs2[0][k], hh1 = hs2[1][k];
            a00 = fma2(w.x, x0, a00);  a01 = fma2(w.y, x0, a01);
            a00 = fma2(u.x, hh0, a00); a01 = fma2(u.y, hh0, a01);
            a10 = fma2(w.x, x1, a10);  a11 = fma2(w.y, x1, a11);
            a10 = fma2(u.x, hh1, a10); a11 = fma2(u.y, hh1, a11);
        }
        *(ull*)&gp[khalf][0][cbase]   = a00;
        *(ull*)&gp[khalf][0][cbase+2] = a01;
        *(ull*)&gp[khalf][1][cbase]   = a10;
        *(ull*)&gp[khalf][1][cbase+2] = a11;
        __syncthreads();

        // activations: 256 outputs (2 batches x 128)
        {
            int bb = tid >> 7, i = tid & 127;
            const float* bb_l = bL + l*FOURH;
            float ig = gp[0][bb][i]       + gp[1][bb][i]       + bb_l[i];
            float fg = gp[0][bb][128 + i] + gp[1][bb][128 + i] + bb_l[128 + i];
            float gg = gp[0][bb][256 + i] + gp[1][bb][256 + i] + bb_l[256 + i];
            float og = gp[0][bb][384 + i] + gp[1][bb][384 + i] + bb_l[384 + i];
            size_t ofs = ((size_t)l*B + b0 + bb)*H + i;
            float cprev = c0[ofs];
            float cn = sigf(fg)*cprev + sigf(ig)*tanhf(gg);
            float hn = sigf(og)*tanhf(cn);
            out[OFF_C + ofs] = cn;
            out[OFF_H + ofs] = hn;
            xs2[bb][i] = bcast2(hn);   // next-layer input; guarded by sync at loop top
        }
    }
    __syncthreads();

    for (int idx = tid; idx < 2*H; idx += 256) {
        int bb = idx >> 7, i = idx & 127;
        g_x[(b0+bb)*H + i] = ((const float2*)&xs2[bb][i])->x;
    }

    // q[bb][j] = x . Wq[:,j] + bq[j]
    {
        int bb = tid >> 7, j = tid & 127;
        float acc = bq[j];
#pragma unroll 8
        for (int i = 0; i < H; i++)
            acc += ((const float2*)&xs2[bb][i])->x * Wq[i*H + j];
        qs[bb][j] = acc;
    }
    __syncthreads();

    // r[bb][i] = Wk[i,:] . q[bb]  (warp per row)
    int wid = tid >> 5, lane = tid & 31;
    for (int row = wid; row < 2*H; row += 8) {
        int bb = row >> 7, i = row & 127;
        float4 wv = ((const float4*)(Wk + (size_t)i*H))[lane];
        float4 qv = ((const float4*)qs[bb])[lane];
        float d = wv.x*qv.x + wv.y*qv.y + wv.z*qv.z + wv.w*qv.w;
        d = warp_sum(d);
        if (lane == 0) g_r[(b0+bb)*H + i] = d;
    }
    if (wid < 2) {
        int bb = wid;
        float p = 0.f;
        for (int j = lane; j < H; j += 32) p += bk[j] * qs[bb][j];
        p = warp_sum(p);
        if (lane == 0) g_cK[b0+bb] = p;
    }
}

// ==== K2: fused attn_mem copy + flash pass (split-S, latency-overlapped) ===
// grid (CHUNKS, B), 256 threads = 8 warps, 8 rows per warp, one float4/lane.
__global__ __launch_bounds__(256) void k_attn_copy(
    const float* __restrict__ attn_mem, const int* __restrict__ step_p,
    float* __restrict__ out)
{
    __shared__ float sm_acc[8][H];
    __shared__ float sm_m[8], sm_l[8];

    int b = blockIdx.y;
    int chunk = blockIdx.x;
    int step = *step_p;
    int tid = threadIdx.x, wid = tid >> 5, lane = tid & 31;
    int base = chunk*ROWS + wid*8;

    const float4* src = (const float4*)(attn_mem + (size_t)b*S*H);
    float4* dst = (float4*)(out + OFF_ATTN + (size_t)b*S*H);

    if (chunk*ROWS > step) {
        // pure copy: streaming loads/stores, no L2 retention
        float4 v[8];
#pragma unroll
        for (int t = 0; t < 8; t++) v[t] = __ldcs(&src[(size_t)(base+t)*32 + lane]);
#pragma unroll
        for (int t = 0; t < 8; t++) __stcs(&dst[(size_t)(base+t)*32 + lane], v[t]);
        return;
    }

    const float4* xr = (const float4*)(g_x + b*H);
    float4 rf = ((const float4*)(g_r + b*H))[lane];
    float cK = g_cK[b];
    const float scl = 0.08838834764831843f;   // 1/sqrt(128)

    float4 v[8];
#pragma unroll
    for (int t = 0; t < 8; t++) {
        int s = base + t;
        v[t] = (s == step) ? xr[lane] : __ldcs(&src[(size_t)s*32 + lane]);
    }
#pragma unroll
    for (int t = 0; t < 8; t++) __stcs(&dst[(size_t)(base+t)*32 + lane], v[t]);

    // 8 independent partial dots, then 8 interleaved butterfly reductions
    float d[8];
#pragma unroll
    for (int t = 0; t < 8; t++)
        d[t] = v[t].x*rf.x + v[t].y*rf.y + v[t].z*rf.z + v[t].w*rf.w;
#pragma unroll
    for (int o = 16; o > 0; o >>= 1) {
#pragma unroll
        for (int t = 0; t < 8; t++)
            d[t] += __shfl_xor_sync(0xffffffffu, d[t], o);
    }

    // max-first softmax over the warp's 8 rows (no serial rescale chain)
    float sct[8];
    float m = -INFINITY;
#pragma unroll
    for (int t = 0; t < 8; t++) {
        sct[t] = (base + t <= step) ? (d[t] + cK) * scl : -INFINITY;
        m = fmaxf(m, sct[t]);
    }
    float l = 0.f;
    float4 acc = {0.f, 0.f, 0.f, 0.f};
#pragma unroll
    for (int t = 0; t < 8; t++) {
        float w = (base + t <= step) ? __expf(sct[t] - m) : 0.f;
        l += w;
        acc.x += w*v[t].x; acc.y += w*v[t].y;
        acc.z += w*v[t].z; acc.w += w*v[t].w;
    }
    ((float4*)sm_acc[wid])[lane] = acc;
    if (lane == 0) { sm_m[wid] = m; sm_l[wid] = l; }
    __syncthreads();

    if (tid < H) {
        float M = sm_m[0];
#pragma unroll
        for (int w = 1; w < 8; w++) M = fmaxf(M, sm_m[w]);
        float a = 0.f, L = 0.f;
#pragma unroll
        for (int w = 0; w < 8; w++) {
            float e = __expf(sm_m[w] - M);   // exp(-inf - finite) = 0
            a += sm_acc[w][tid] * e;
            L += sm_l[w] * e;
        }
        g_pacc[((size_t)b*CHUNKS + chunk)*H + tid] = a;
        if (tid == 0) { g_pm[b*CHUNKS + chunk] = M; g_pl[b*CHUNKS + chunk] = L; }
    }
}

// ==== K3: combine partials -> ctx -> mix -> tanh -> LayerNorm ============
// 256 threads: dot-product i-ranges split across two 128-thread halves.
__global__ __launch_bounds__(256) void k_reduce_mix(
    const int* __restrict__ step_p,
    const float* __restrict__ Wv, const float* __restrict__ bv,
    const float* __restrict__ Wmix, const float* __restrict__ bmix,
    const float* __restrict__ lns, const float* __restrict__ lnb)
{
    __shared__ float es[CHUNKS];
    __shared__ float red[128];
    __shared__ float part[256];
    __shared__ float cp[H], xsm[H], ctxs[H];

    int b = blockIdx.x;
    int tid = threadIdx.x;
    int t = tid & 127, half = tid >> 7;
    int nact = (*step_p >> 6) + 1;   // chunks [0, nact) touched attention

    if (tid < 128) {
        float pm = (tid < nact) ? g_pm[b*CHUNKS + tid] : -INFINITY;
        red[tid] = pm;
    }
    __syncthreads();
    for (int o = 64; o > 0; o >>= 1) {
        if (tid < o) red[tid] = fmaxf(red[tid], red[tid+o]);
        __syncthreads();
    }
    float M = red[0];
    __syncthreads();

    if (tid < 128) {
        float pm = (tid < nact) ? g_pm[b*CHUNKS + tid] : -INFINITY;
        float pl = (tid < nact) ? g_pl[b*CHUNKS + tid] : 0.f;
        float e = __expf(pm - M);    // pm=-inf -> 0
        es[tid] = e;
        red[tid] = pl * e;
    }
    __syncthreads();
    for (int o = 64; o > 0; o >>= 1) {
        if (tid < o) red[tid] += red[tid+o];
        __syncthreads();
    }
    float L = red[0];
    __syncthreads();

    // combine partial accumulators: chunk range split by half
    {
        float a = 0.f;
#pragma unroll 4
        for (int c = half; c < nact; c += 2)
            a += g_pacc[((size_t)b*CHUNKS + c)*H + t] * es[c];
        part[tid] = a;
    }
    __syncthreads();
    if (tid < 128) {
        cp[t] = (part[t] + part[t+128]) / L;
        xsm[t] = g_x[b*H + t];
    }
    __syncthreads();

    // ctx = cp @ Wv + bv, split i
    {
        float cv = 0.f;
        int i0 = half*64;
#pragma unroll 8
        for (int i = i0; i < i0 + 64; i++) cv += cp[i] * Wv[i*H + t];
        part[tid] = cv;
    }
    __syncthreads();
    if (tid < 128) ctxs[t] = part[t] + part[t+128] + bv[t];
    __syncthreads();

    // h_mix = tanh([x; ctx] @ Wmix + bmix), split i over 256
    {
        float hm = 0.f;
        if (half == 0) {
#pragma unroll 8
            for (int i = 0; i < 128; i++) hm += xsm[i] * Wmix[i*H + t];
        } else {
#pragma unroll 8
            for (int i = 0; i < 128; i++) hm += ctxs[i] * Wmix[(H+i)*H + t];
        }
        part[tid] = hm;
    }
    __syncthreads();

    float hv = 0.f;
    if (tid < 128) {
        hv = tanhf(part[t] + part[t+128] + bmix[t]);
        red[t] = hv;
    }
    __syncthreads();
    for (int o = 64; o > 0; o >>= 1) {
        if (tid < o) red[tid] += red[tid+o];
        __syncthreads();
    }
    float mu = red[0] * (1.f/128.f);
    __syncthreads();
    float dv = hv - mu;
    if (tid < 128) red[t] = dv*dv;
    __syncthreads();
    for (int o = 64; o > 0; o >>= 1) {
        if (tid < o) red[tid] += red[tid+o];
        __syncthreads();
    }
    float var = red[0] * (1.f/128.f);

    if (tid < 128)
        g_hln[b*H + t] = dv * rsqrtf(var + 1e-6f) * lns[t] + lnb[t];
}

// ==== K4: logits = h_ln @ Wout + bout; 1 col x 16 batches / thread ========
// grid (ceil(V/256), 4). Software-pipelined Wout prefetch (8-deep).
__global__ __launch_bounds__(256) void k_logits(
    const float* __restrict__ Wout, const float* __restrict__ bout,
    float* __restrict__ out)
{
    __shared__ ull hsu[H*8];   // [k][batch-pair] for this 16-batch quarter: 8KB
    int tid = threadIdx.x;
    int bq = blockIdx.y;       // batches [bq*16, bq*16+16)
    float* hsf = (float*)hsu;
    for (int idx = tid; idx < 16*H; idx += 256) {
        int k = idx >> 4, bb = idx & 15;
        hsf[k*16 + bb] = g_hln[(bq*16 + bb)*H + k];
    }
    __syncthreads();

    int c = blockIdx.x*256 + tid;
    int ok = (c < V);
    int cc = ok ? c : (V-1);
    const float* wp = Wout + cc;

    ull acc[8];
#pragma unroll
    for (int i = 0; i < 8; i++) acc[i] = 0ULL;

    // software pipeline: 8 weights in flight while FMA-ing previous 8
    float wbuf[8];
#pragma unroll
    for (int kk = 0; kk < 8; kk++) wbuf[kk] = wp[(size_t)kk*V];

#pragma unroll 1
    for (int k0 = 0; k0 < H; k0 += 8) {
        float wn[8];
        if (k0 + 8 < H) {
#pragma unroll
            for (int kk = 0; kk < 8; kk++) wn[kk] = wp[(size_t)(k0+8+kk)*V];
        }
#pragma unroll
        for (int kk = 0; kk < 8; kk++) {
            ull w2 = bcast2(wbuf[kk]);
            const ulonglong2* hp = (const ulonglong2*)(hsu + (k0+kk)*8);
#pragma unroll
            for (int p = 0; p < 4; p++) {
                ulonglong2 hv = hp[p];   // lane-invariant: LDS broadcast
                acc[2*p]   = fma2(hv.x, w2, acc[2*p]);
                acc[2*p+1] = fma2(hv.y, w2, acc[2*p+1]);
            }
        }
#pragma unroll
        for (int kk = 0; kk < 8; kk++) wbuf[kk] = wn[kk];
    }

    if (ok) {
        float bo = bout[cc];
#pragma unroll
        for (int p = 0; p < 8; p++) {
            float f0, f1;
            asm("mov.b64 {%0, %1}, %2;" : "=f"(f0), "=f"(f1) : "l"(acc[p]));
            int b0r = bq*16 + 2*p;
            out[(size_t)b0r*V + c]     = f0 + bo;
            out[(size_t)(b0r+1)*V + c] = f1 + bo;
        }
    }
}

// ==========================================================================
extern "C" void kernel_launch(void* const* d_in, const int* in_sizes, int n_in,
                              void* d_out, int out_size)
{
    const int*   token_id = (const int*)  d_in[0];
    const float* c0       = (const float*)d_in[1];
    const float* h0       = (const float*)d_in[2];
    const float* attn_mem = (const float*)d_in[3];
    const int*   step_p   = (const int*)  d_in[4];
    const float* emb      = (const float*)d_in[5];
    const float* Wi       = (const float*)d_in[6];
    const float* Uh       = (const float*)d_in[7];
    const float* bL       = (const float*)d_in[8];
    const float* Wq       = (const float*)d_in[9];
    const float* bq       = (const float*)d_in[10];
    const float* Wk       = (const float*)d_in[11];
    const float* bk       = (const float*)d_in[12];
    const float* Wv       = (const float*)d_in[13];
    const float* bv       = (const float*)d_in[14];
    const float* Wmix     = (const float*)d_in[15];
    const float* bmix     = (const float*)d_in[16];
    const float* lns      = (const float*)d_in[17];
    const float* lnb      = (const float*)d_in[18];
    const float* Wout     = (const float*)d_in[19];
    const float* bout     = (const float*)d_in[20];
    float* out = (float*)d_out;

    k_lstm<<<32, 256>>>(token_id, c0, h0, emb, Wi, Uh, bL, Wq, bq, Wk, bk, out);
    dim3 g2(CHUNKS, B);
    k_attn_copy<<<g2, 256>>>(attn_mem, step_p, out);
    k_reduce_mix<<<B, 256>>>(step_p, Wv, bv, Wmix, bmix, lns, lnb);
    dim3 g4((V + 255)/256, 4);
    k_logits<<<g4, 256>>>(Wout, bout, out);
}

// round 11
// speedup vs baseline: 1.3101x; 1.1016x over previous
#include <cuda_runtime.h>
#include <math.h>

#define B 64
#define H 128
#define E 128
#define NL 4
#define S 8192
#define V 50257
#define FOURH 512
#define CHUNKS 128   // S / ROWS
#define ROWS 64

#define SZ_LOGITS (B*V)
#define OFF_C  (SZ_LOGITS)
#define OFF_H  (OFF_C + NL*B*H)
#define OFF_ATTN (OFF_H + NL*B*H)

typedef unsigned long long ull;

// ---------------- device scratch (no allocations allowed) ----------------
__device__ __align__(16) float g_x[B*H];          // final hidden (x)
__device__ __align__(16) float g_r[B*H];          // Wk @ q  per batch
__device__ float g_cK[B];                          // bk . q
__device__ float g_pl[B*CHUNKS];                   // partial exp-sums
__device__ __align__(16) float g_pacc[B*CHUNKS*H]; // partial weighted sums
__device__ __align__(16) float g_hln[B*H];
__device__ int g_cnt[B];                           // per-batch done counters

__device__ __forceinline__ float warp_sum(float v) {
#pragma unroll
    for (int o = 16; o > 0; o >>= 1) v += __shfl_xor_sync(0xffffffffu, v, o);
    return v;
}
__device__ __forceinline__ float sigf(float x) { return 1.f / (1.f + __expf(-x)); }

__device__ __forceinline__ ull fma2(ull a, ull b, ull c) {
    ull d;
    asm("fma.rn.f32x2 %0, %1, %2, %3;" : "=l"(d) : "l"(a), "l"(b), "l"(c));
    return d;
}
__device__ __forceinline__ ull bcast2(float f) {
    ull d;
    asm("mov.b64 %0, {%1, %1};" : "=l"(d) : "f"(f));
    return d;
}

// ============ K1: embed + 4-layer LSTM + q, r = Wk@q, cK = bk.q ============
// 32 blocks x 256 threads, 2 batches per block, f32x2 FMAs.
// Also resets g_cnt for this launch (stream-serialized before k_attn_copy).
__global__ __launch_bounds__(256) void k_lstm(
    const int* __restrict__ token_id, const float* __restrict__ c0,
    const float* __restrict__ h0, const float* __restrict__ emb,
    const float* __restrict__ Wi, const float* __restrict__ Uh,
    const float* __restrict__ bL, const float* __restrict__ Wq,
    const float* __restrict__ bq, const float* __restrict__ Wk,
    const float* __restrict__ bk, float* __restrict__ out)
{
    __shared__ ull xs2[2][H];              // {x,x} broadcast pairs
    __shared__ ull hs2[2][H];              // {h,h} broadcast pairs
    __shared__ float gp[2][2][FOURH];      // [k-half][bb][col]
    __shared__ float qs[2][H];

    int tid = threadIdx.x;
    int b0 = blockIdx.x * 2;

    if (tid == 0) { g_cnt[b0] = 0; g_cnt[b0+1] = 0; }

    for (int idx = tid; idx < 2*H; idx += 256) {
        int bb = idx >> 7, i = idx & 127;
        float v = emb[(size_t)token_id[b0+bb]*E + i];
        xs2[bb][i] = bcast2(v);
    }

    int khalf = tid >> 7;        // 0 or 1: which half of k
    int tc = tid & 127;          // column group: cols [4tc, 4tc+4)
    int cbase = tc * 4;

    for (int l = 0; l < NL; l++) {
        for (int idx = tid; idx < 2*H; idx += 256) {
            int bb = idx >> 7, i = idx & 127;
            float v = h0[((size_t)l*B + b0 + bb)*H + i];
            hs2[bb][i] = bcast2(v);
        }
        __syncthreads();

        ull a00 = 0, a01 = 0, a10 = 0, a11 = 0;
        const ulonglong2* Wi2 = (const ulonglong2*)(Wi + (size_t)l*E*FOURH);
        const ulonglong2* Uh2 = (const ulonglong2*)(Uh + (size_t)l*H*FOURH);
        int k0 = khalf * 64;
#pragma unroll 4
        for (int k = k0; k < k0 + 64; k++) {
            ulonglong2 w = Wi2[k*(FOURH/4) + tc];
            ulonglong2 u = Uh2[k*(FOURH/4) + tc];
            ull x0 = xs2[0][k], x1 = xs2[1][k];
            ull hh0 = hs2[0][k], hh1 = hs2[1][k];
            a00 = fma2(w.x, x0, a00);  a01 = fma2(w.y, x0, a01);
            a00 = fma2(u.x, hh0, a00); a01 = fma2(u.y, hh0, a01);
            a10 = fma2(w.x, x1, a10);  a11 = fma2(w.y, x1, a11);
            a10 = fma2(u.x, hh1, a10); a11 = fma2(u.y, hh1, a11);
        }
        *(ull*)&gp[khalf][0][cbase]   = a00;
        *(ull*)&gp[khalf][0][cbase+2] = a01;
        *(ull*)&gp[khalf][1][cbase]   = a10;
        *(ull*)&gp[khalf][1][cbase+2] = a11;
        __syncthreads();

        // activations: 256 outputs (2 batches x 128)
        {
            int bb = tid >> 7, i = tid & 127;
            const float* bb_l = bL + l*FOURH;
            float ig = gp[0][bb][i]       + gp[1][bb][i]       + bb_l[i];
            float fg = gp[0][bb][128 + i] + gp[1][bb][128 + i] + bb_l[128 + i];
            float gg = gp[0][bb][256 + i] + gp[1][bb][256 + i] + bb_l[256 + i];
            float og = gp[0][bb][384 + i] + gp[1][bb][384 + i] + bb_l[384 + i];
            size_t ofs = ((size_t)l*B + b0 + bb)*H + i;
            float cprev = c0[ofs];
            float cn = sigf(fg)*cprev + sigf(ig)*tanhf(gg);
            float hn = sigf(og)*tanhf(cn);
            out[OFF_C + ofs] = cn;
            out[OFF_H + ofs] = hn;
            xs2[bb][i] = bcast2(hn);   // next-layer input; guarded by sync at loop top
        }
    }
    __syncthreads();

    for (int idx = tid; idx < 2*H; idx += 256) {
        int bb = idx >> 7, i = idx & 127;
        g_x[(b0+bb)*H + i] = ((const float2*)&xs2[bb][i])->x;
    }

    // q[bb][j] = x . Wq[:,j] + bq[j]
    {
        int bb = tid >> 7, j = tid & 127;
        float acc = bq[j];
#pragma unroll 8
        for (int i = 0; i < H; i++)
            acc += ((const float2*)&xs2[bb][i])->x * Wq[i*H + j];
        qs[bb][j] = acc;
    }
    __syncthreads();

    // r[bb][i] = Wk[i,:] . q[bb]  (warp per row)
    int wid = tid >> 5, lane = tid & 31;
    for (int row = wid; row < 2*H; row += 8) {
        int bb = row >> 7, i = row & 127;
        float4 wv = ((const float4*)(Wk + (size_t)i*H))[lane];
        float4 qv = ((const float4*)qs[bb])[lane];
        float d = wv.x*qv.x + wv.y*qv.y + wv.z*qv.z + wv.w*qv.w;
        d = warp_sum(d);
        if (lane == 0) g_r[(b0+bb)*H + i] = d;
    }
    if (wid < 2) {
        int bb = wid;
        float p = 0.f;
        for (int j = lane; j < H; j += 32) p += bk[j] * qs[bb][j];
        p = warp_sum(p);
        if (lane == 0) g_cK[b0+bb] = p;
    }
}

// ============ inline reduce for one batch (last-done block runs this) =====
// No-max softmax combine: L = sum pl, ctx = sum pacc / L, then mix + LN.
__device__ __noinline__ void reduce_batch(
    int b, int nact,
    float* s_red, float* s_part, float* s_cp, float* s_xsm, float* s_ctx,
    const float* __restrict__ Wv, const float* __restrict__ bv,
    const float* __restrict__ Wmix, const float* __restrict__ bmix,
    const float* __restrict__ lns, const float* __restrict__ lnb)
{
    int tid = threadIdx.x;
    int t = tid & 127, half = tid >> 7;

    // L = sum of per-chunk exp-sums
    if (tid < 128)
        s_red[tid] = (tid < nact) ? g_pl[b*CHUNKS + tid] : 0.f;
    __syncthreads();
    for (int o = 64; o > 0; o >>= 1) {
        if (tid < o) s_red[tid] += s_red[tid+o];
        __syncthreads();
    }
    float L = s_red[0];
    __syncthreads();

    // combine partial accumulators (fixed order per half -> deterministic)
    {
        float a = 0.f;
#pragma unroll 4
        for (int c = half; c < nact; c += 2)
            a += g_pacc[((size_t)b*CHUNKS + c)*H + t];
        s_part[tid] = a;
    }
    __syncthreads();
    if (tid < 128) {
        s_cp[t] = (s_part[t] + s_part[t+128]) / L;
        s_xsm[t] = g_x[b*H + t];
    }
    __syncthreads();

    // ctx = cp @ Wv + bv, split i across halves
    {
        float cv = 0.f;
        int i0 = half*64;
#pragma unroll 8
        for (int i = i0; i < i0 + 64; i++) cv += s_cp[i] * Wv[i*H + t];
        s_part[tid] = cv;
    }
    __syncthreads();
    if (tid < 128) s_ctx[t] = s_part[t] + s_part[t+128] + bv[t];
    __syncthreads();

    // h_mix = tanh([x; ctx] @ Wmix + bmix)
    {
        float hm = 0.f;
        if (half == 0) {
#pragma unroll 8
            for (int i = 0; i < 128; i++) hm += s_xsm[i] * Wmix[i*H + t];
        } else {
#pragma unroll 8
            for (int i = 0; i < 128; i++) hm += s_ctx[i] * Wmix[(H+i)*H + t];
        }
        s_part[tid] = hm;
    }
    __syncthreads();

    float hv = 0.f;
    if (tid < 128) {
        hv = tanhf(s_part[t] + s_part[t+128] + bmix[t]);
        s_red[t] = hv;
    }
    __syncthreads();
    for (int o = 64; o > 0; o >>= 1) {
        if (tid < o) s_red[tid] += s_red[tid+o];
        __syncthreads();
    }
    float mu = s_red[0] * (1.f/128.f);
    __syncthreads();
    float dv = hv - mu;
    if (tid < 128) s_red[t] = dv*dv;
    __syncthreads();
    for (int o = 64; o > 0; o >>= 1) {
        if (tid < o) s_red[tid] += s_red[tid+o];
        __syncthreads();
    }
    float var = s_red[0] * (1.f/128.f);

    if (tid < 128)
        g_hln[b*H + t] = dv * rsqrtf(var + 1e-6f) * lns[t] + lnb[t];
}

// ==== K2: fused attn_mem copy + flash pass + inline per-batch reduce ======
// grid (CHUNKS, B), 256 threads = 8 warps, 8 rows per warp.
__global__ __launch_bounds__(256) void k_attn_copy(
    const float* __restrict__ attn_mem, const int* __restrict__ step_p,
    const float* __restrict__ Wv, const float* __restrict__ bv,
    const float* __restrict__ Wmix, const float* __restrict__ bmix,
    const float* __restrict__ lns, const float* __restrict__ lnb,
    float* __restrict__ out)
{
    __shared__ float sm_acc[8][H];
    __shared__ float sm_l[8];
    __shared__ int sm_last;
    __shared__ float s_red[128], s_part[256], s_cp[H], s_xsm[H], s_ctx[H];

    int b = blockIdx.y;
    int chunk = blockIdx.x;
    int step = *step_p;
    int tid = threadIdx.x, wid = tid >> 5, lane = tid & 31;
    int base = chunk*ROWS + wid*8;

    const float4* src = (const float4*)(attn_mem + (size_t)b*S*H);
    float4* dst = (float4*)(out + OFF_ATTN + (size_t)b*S*H);

    if (chunk*ROWS > step) {
        // pure copy: streaming loads/stores, no L2 retention
        float4 v[8];
#pragma unroll
        for (int t = 0; t < 8; t++) v[t] = __ldcs(&src[(size_t)(base+t)*32 + lane]);
#pragma unroll
        for (int t = 0; t < 8; t++) __stcs(&dst[(size_t)(base+t)*32 + lane], v[t]);
        return;
    }

    const float4* xr = (const float4*)(g_x + b*H);
    float4 rf = ((const float4*)(g_r + b*H))[lane];
    float cK = g_cK[b];
    const float scl = 0.08838834764831843f;   // 1/sqrt(128)

    float4 v[8];
#pragma unroll
    for (int t = 0; t < 8; t++) {
        int s = base + t;
        v[t] = (s == step) ? xr[lane] : __ldcs(&src[(size_t)s*32 + lane]);
    }
#pragma unroll
    for (int t = 0; t < 8; t++) __stcs(&dst[(size_t)(base+t)*32 + lane], v[t]);

    // 8 independent partial dots, then 8 interleaved butterfly reductions
    float d[8];
#pragma unroll
    for (int t = 0; t < 8; t++)
        d[t] = v[t].x*rf.x + v[t].y*rf.y + v[t].z*rf.z + v[t].w*rf.w;
#pragma unroll
    for (int o = 16; o > 0; o >>= 1) {
#pragma unroll
        for (int t = 0; t < 8; t++)
            d[t] += __shfl_xor_sync(0xffffffffu, d[t], o);
    }

    // no-max softmax partials: scores are O(1), fp32 exp is safe
    float l = 0.f;
    float4 acc = {0.f, 0.f, 0.f, 0.f};
#pragma unroll
    for (int t = 0; t < 8; t++) {
        float w = (base + t <= step) ? __expf((d[t] + cK) * scl) : 0.f;
        l += w;
        acc.x += w*v[t].x; acc.y += w*v[t].y;
        acc.z += w*v[t].z; acc.w += w*v[t].w;
    }
    ((float4*)sm_acc[wid])[lane] = acc;
    if (lane == 0) sm_l[wid] = l;
    __syncthreads();

    if (tid < H) {
        float a = 0.f;
#pragma unroll
        for (int w = 0; w < 8; w++) a += sm_acc[w][tid];
        g_pacc[((size_t)b*CHUNKS + chunk)*H + tid] = a;
    }
    if (tid == 0) {
        float L = 0.f;
#pragma unroll
        for (int w = 0; w < 8; w++) L += sm_l[w];
        g_pl[b*CHUNKS + chunk] = L;
    }

    // last-done block for this batch runs the reduce inline
    int nact = (step >> 6) + 1;
    __threadfence();                 // publish pacc/pl (all threads)
    __syncthreads();
    if (tid == 0) {
        int old = atomicAdd(&g_cnt[b], 1);
        sm_last = (old == nact - 1);
    }
    __syncthreads();
    if (sm_last) {
        __threadfence();             // acquire: see all blocks' partials
        reduce_batch(b, nact, s_red, s_part, s_cp, s_xsm, s_ctx,
                     Wv, bv, Wmix, bmix, lns, lnb);
    }
}

// ==== K4: logits = h_ln @ Wout + bout; 2 cols (c, c+256) x 16 batches =====
// grid (ceil(V/512), 4) — the R3-measured optimum shape.
__global__ __launch_bounds__(256, 3) void k_logits(
    const float* __restrict__ Wout, const float* __restrict__ bout,
    float* __restrict__ out)
{
    __shared__ ull hsu[H*8];   // [k][batch-pair] for this 16-batch quarter: 8KB
    int tid = threadIdx.x;
    int bq = blockIdx.y;       // batches [bq*16, bq*16+16)
    float* hsf = (float*)hsu;
    for (int idx = tid; idx < 16*H; idx += 256) {
        int k = idx >> 4, bb = idx & 15;
        hsf[k*16 + bb] = g_hln[(bq*16 + bb)*H + k];
    }
    __syncthreads();

    int base = blockIdx.x * 512;
    int ca = base + tid;            // column A
    int cb = ca + 256;              // column B
    int ca_ok = (ca < V), cb_ok = (cb < V);
    int ca_c = ca_ok ? ca : (V-1);
    int cb_c = cb_ok ? cb : (V-1);

    ull acc0[8], acc1[8];
#pragma unroll
    for (int i = 0; i < 8; i++) { acc0[i] = 0ULL; acc1[i] = 0ULL; }

#pragma unroll 4
    for (int k = 0; k < H; k++) {
        float wa = Wout[(size_t)k*V + ca_c];
        float wb = Wout[(size_t)k*V + cb_c];
        ull w2a = bcast2(wa);
        ull w2b = bcast2(wb);
        const ulonglong2* hp = (const ulonglong2*)(hsu + k*8);
#pragma unroll
        for (int p = 0; p < 4; p++) {
            ulonglong2 hv = hp[p];
            acc0[2*p]   = fma2(hv.x, w2a, acc0[2*p]);
            acc0[2*p+1] = fma2(hv.y, w2a, acc0[2*p+1]);
            acc1[2*p]   = fma2(hv.x, w2b, acc1[2*p]);
            acc1[2*p+1] = fma2(hv.y, w2b, acc1[2*p+1]);
        }
    }

    if (ca_ok) {
        float bo = bout[ca_c];
#pragma unroll
        for (int p = 0; p < 8; p++) {
            float f0, f1;
            asm("mov.b64 {%0, %1}, %2;" : "=f"(f0), "=f"(f1) : "l"(acc0[p]));
            int b0r = bq*16 + 2*p;
            out[(size_t)b0r*V + ca]     = f0 + bo;
            out[(size_t)(b0r+1)*V + ca] = f1 + bo;
        }
    }
    if (cb_ok) {
        float bo = bout[cb_c];
#pragma unroll
        for (int p = 0; p < 8; p++) {
            float f0, f1;
            asm("mov.b64 {%0, %1}, %2;" : "=f"(f0), "=f"(f1) : "l"(acc1[p]));
            int b0r = bq*16 + 2*p;
            out[(size_t)b0r*V + cb]     = f0 + bo;
            out[(size_t)(b0r+1)*V + cb] = f1 + bo;
        }
    }
}

// ==========================================================================
extern "C" void kernel_launch(void* const* d_in, const int* in_sizes, int n_in,
                              void* d_out, int out_size)
{
    const int*   token_id = (const int*)  d_in[0];
    const float* c0       = (const float*)d_in[1];
    const float* h0       = (const float*)d_in[2];
    const float* attn_mem = (const float*)d_in[3];
    const int*   step_p   = (const int*)  d_in[4];
    const float* emb      = (const float*)d_in[5];
    const float* Wi       = (const float*)d_in[6];
    const float* Uh       = (const float*)d_in[7];
    const float* bL       = (const float*)d_in[8];
    const float* Wq       = (const float*)d_in[9];
    const float* bq       = (const float*)d_in[10];
    const float* Wk       = (const float*)d_in[11];
    const float* bk       = (const float*)d_in[12];
    const float* Wv       = (const float*)d_in[13];
    const float* bv       = (const float*)d_in[14];
    const float* Wmix     = (const float*)d_in[15];
    const float* bmix     = (const float*)d_in[16];
    const float* lns      = (const float*)d_in[17];
    const float* lnb      = (const float*)d_in[18];
    const float* Wout     = (const float*)d_in[19];
    const float* bout     = (const float*)d_in[20];
    float* out = (float*)d_out;

    k_lstm<<<32, 256>>>(token_id, c0, h0, emb, Wi, Uh, bL, Wq, bq, Wk, bk, out);
    dim3 g2(CHUNKS, B);
    k_attn_copy<<<g2, 256>>>(attn_mem, step_p, Wv, bv, Wmix, bmix, lns, lnb, out);
    dim3 g4((V + 511)/512, 4);
    k_logits<<<g4, 256>>>(Wout, bout, out);
}